// round 16
// baseline (speedup 1.0000x reference)
#include <cuda_runtime.h>
#include <math.h>

#define BATCH 4
#define T_IN 1920
#define E_IN 512
#define C1 128
#define T1 640
#define C2 1024
#define T2 128

// Scratch (device globals; allocations forbidden)
__device__ float  g_h1[5 * T1 * C1];             // conv1+ln1+silu output
__device__ float  g_c1p[8][5 * T1 * C1];         // conv1 partials per E-eighth
__device__ float  g_c2p[3][5 * T2 * C2];         // conv2 partials per k-tap
__device__ float  g_sp[T2 * C2];                 // symbol_projected
__device__ float  g_S8[8][BATCH * T2 * T2];      // similarity partials per 128-d chunk
__device__ float2 g_wpk1[5 * 256 * 128];         // conv1 w c-pair packed
__device__ float2 g_wpk2[3 * 64 * 1024];         // conv2 w c-pair packed

__device__ __forceinline__ float silu_f(float y) { return y / (1.0f + expf(-y)); }

__device__ __forceinline__ unsigned long long fma2(unsigned long long a,
                                                   unsigned long long b,
                                                   unsigned long long c) {
    unsigned long long d;
    asm("fma.rn.f32x2 %0, %1, %2, %3;" : "=l"(d) : "l"(a), "l"(b), "l"(c));
    return d;
}
__device__ __forceinline__ float pksum(unsigned long long p) {
    unsigned int lo, hi;
    asm("mov.b64 {%0, %1}, %2;" : "=r"(lo), "=r"(hi) : "l"(p));
    return __uint_as_float(lo) + __uint_as_float(hi);
}

// ---------------------------------------------------------------------------
// Kernels 0a/0b/0c: repack conv weights (split so conv1 is ncu's slot-4).
// ---------------------------------------------------------------------------
__global__ void prepack_w2(const float* __restrict__ w2) {
    int idx = blockIdx.x * 256 + threadIdx.x;      // 768 blocks
    if (idx < 3 * 64 * 1024) {
        int o  = idx & 1023;
        int c2 = (idx >> 10) & 63;
        int k  = idx >> 16;
        const float* p = w2 + ((size_t)(k * 128 + 2 * c2)) * 1024 + o;
        g_wpk2[idx] = make_float2(p[0], p[1024]);
    }
}

__global__ void prepack_w1(const float* __restrict__ w1, int base) {
    int idx = base + blockIdx.x * 256 + threadIdx.x;   // 320 blocks per half
    if (idx < 5 * 256 * 128) {
        int o  = idx & 127;
        int c2 = (idx >> 7) & 255;
        int k  = idx >> 15;
        const float* p = w1 + ((size_t)(k * 512 + 2 * c2)) * 128 + o;
        g_wpk1[idx] = make_float2(p[0], p[128]);
    }
}

// ---------------------------------------------------------------------------
// Kernel A1: conv1 partials with SMEM-STAGED WEIGHTS.
// grid = 5src x 20tg x 8eh = 800 blocks, 256 thr, 4 CTAs/SM.
// 10 stages (5 k x 2 c2-halves): bulk-load 16KB contiguous weight slice,
// then inner loop is pure LDS + FFMA2 (16 wf per 16 fma-cycles).
// ---------------------------------------------------------------------------
#define C1TS 32
#define C1ROWS (3 * (C1TS - 1) + 5)   // 98
#define EC 64

__global__ void __launch_bounds__(256, 4) conv1_raw(const float* __restrict__ values,
                                                    const float* __restrict__ symbols) {
    __shared__ float  xs[C1ROWS * EC];   // 25KB
    __shared__ float2 wsm[16 * 128];     // 16KB: [c2local][ch]

    int blk = blockIdx.x;               // (src*20 + tg)*8 + eh
    int eh  = blk & 7;
    int st  = blk >> 3;                 // 0..99
    int src = st / 20;
    int tg  = st % 20;
    int t0  = tg * C1TS;
    const float* x = (src < 4) ? (values + (size_t)src * T_IN * E_IN) : symbols;
    int base_row = t0 * 3 - 1;
    int col0 = eh * EC;

    int t    = threadIdx.x;
    int lane = t & 31;
    int wrp  = t >> 5;                  // 0..7
    int tsg  = wrp & 3;                 // 4 ts-groups
    int chh  = wrp >> 2;                // 2 channel halves
    int ch0  = chh * 64 + lane * 2;
    int ts0  = tsg * 8;                 // 8 timesteps per warp

    // stage 98 rows x 64 cols of x
    for (int idx = t; idx < C1ROWS * (EC / 4); idx += 256) {
        int r  = idx >> 4;              // EC/4 = 16
        int c4 = idx & 15;
        int gr = base_row + r;
        float4 v = make_float4(0.f, 0.f, 0.f, 0.f);
        if (gr >= 0 && gr < T_IN)
            v = *(const float4*)(x + (size_t)gr * E_IN + col0 + c4 * 4);
        ((float4*)xs)[idx] = v;
    }

    unsigned long long acc[8][2];       // [ts][ch]
#pragma unroll
    for (int j = 0; j < 8; j++) { acc[j][0] = 0ULL; acc[j][1] = 0ULL; }

#pragma unroll
    for (int k = 0; k < 5; k++) {
#pragma unroll
        for (int h = 0; h < 2; h++) {
            __syncthreads();   // x-stage visible (1st iter) / wsm readers done
            // stage 16KB contiguous weight slice: c-pairs [eh*32+h*16, +16), all 128 ch
            const float4* wsrc =
                (const float4*)(g_wpk1 + ((size_t)(k * 256 + eh * 32 + h * 16)) * 128);
#pragma unroll
            for (int i = 0; i < 4; i++)
                ((float4*)wsm)[t + 256 * i] = wsrc[t + 256 * i];
            __syncthreads();

            int xcol = 32 * h;
#pragma unroll 2
            for (int c2 = 0; c2 < 16; c2 += 2) {
                ulonglong2 w0 = *(const ulonglong2*)&wsm[c2 * 128 + ch0];        // c-pair c2
                ulonglong2 w1 = *(const ulonglong2*)&wsm[(c2 + 1) * 128 + ch0];  // c-pair c2+1
#pragma unroll
                for (int j = 0; j < 8; j++) {
                    ulonglong2 xv = *(const ulonglong2*)
                        &xs[(3 * (ts0 + j) + k) * EC + xcol + 2 * c2];
                    acc[j][0] = fma2(xv.x, w0.x, acc[j][0]);
                    acc[j][1] = fma2(xv.x, w0.y, acc[j][1]);
                    acc[j][0] = fma2(xv.y, w1.x, acc[j][0]);
                    acc[j][1] = fma2(xv.y, w1.y, acc[j][1]);
                }
            }
        }
    }

    float* outp = g_c1p[eh];
#pragma unroll
    for (int j = 0; j < 8; j++) {
        float2 o2 = make_float2(pksum(acc[j][0]), pksum(acc[j][1]));
        *(float2*)&outp[((size_t)src * T1 + (t0 + ts0 + j)) * C1 + ch0] = o2;
    }
}

// ---------------------------------------------------------------------------
// Kernel A2: sum conv1 partials + bias + layernorm(128) + silu -> g_h1
// 400 blocks x 256 thr; warp = 1 row, lane = 4 channels (warp-local LN).
// ---------------------------------------------------------------------------
__global__ void ln1_silu(const float* __restrict__ bias,
                         const float* __restrict__ lng,
                         const float* __restrict__ lnb) {
    int row  = blockIdx.x * 8 + (threadIdx.x >> 5);   // 0..3199
    int lane = threadIdx.x & 31;
    int ch0  = lane * 4;
    size_t off = (size_t)row * C1 + ch0;

    float4 v = *(const float4*)&bias[ch0];
#pragma unroll
    for (int eh = 0; eh < 8; eh++) {
        float4 p = *(const float4*)&g_c1p[eh][off];
        v.x += p.x; v.y += p.y; v.z += p.z; v.w += p.w;
    }
    float s  = v.x + v.y + v.z + v.w;
    float s2 = v.x * v.x + v.y * v.y + v.z * v.z + v.w * v.w;
#pragma unroll
    for (int o = 16; o; o >>= 1) {
        s  += __shfl_xor_sync(0xffffffffu, s,  o);
        s2 += __shfl_xor_sync(0xffffffffu, s2, o);
    }
    float m   = s * (1.0f / C1);
    float var = s2 * (1.0f / C1) - m * m;
    float rs  = rsqrtf(var + 1e-3f);
    float4 g4 = *(const float4*)&lng[ch0];
    float4 b4 = *(const float4*)&lnb[ch0];
    float4 o4;
    o4.x = silu_f((v.x - m) * rs * g4.x + b4.x);
    o4.y = silu_f((v.y - m) * rs * g4.y + b4.y);
    o4.z = silu_f((v.z - m) * rs * g4.z + b4.z);
    o4.w = silu_f((v.w - m) * rs * g4.w + b4.w);
    *(float4*)&g_h1[off] = o4;
}

// ---------------------------------------------------------------------------
// Kernel B1: conv2 partials, smem-staged weights (exact R9 best-total config).
// grid = 20 rowgroups(32 rows) x 16 chq(64 ch) x 3 k = 960 blocks, 256 thr.
// ---------------------------------------------------------------------------
__global__ void __launch_bounds__(256, 4) conv2_raw() {
    __shared__ ulonglong2 wsm[64][32];   // [c2][chpair]   32KB
    __shared__ float xs[32 * C1];        // 32 input rows  16KB

    int blk = blockIdx.x;
    int k   = blk % 3;
    int r1  = blk / 3;               // 0..319
    int chq = r1 & 15;               // 16 channel slices of 64
    int rg  = r1 >> 4;               // 0..19
    int R0  = rg * 32;               // global output row (src*T2 + t2)
    int src = R0 >> 7;
    int t0  = R0 & 127;
    int chb = chq * 64;

    int t      = threadIdx.x;
    int chpair = t & 31;             // ch = chb + 2*chpair (+1)
    int jq     = t >> 5;             // 0..7 -> rows jq*4 .. jq*4+3

    // stage weights: 64 c2 x 32 chpairs (each ull2 = two adjacent float2)
    {
        const float2* wsrc = g_wpk2 + (size_t)(k * 64) * 1024 + chb;
        for (int idx = t; idx < 64 * 32; idx += 256) {
            int c2 = idx >> 5, cp = idx & 31;
            wsm[c2][cp] = *(const ulonglong2*)(wsrc + (size_t)c2 * 1024 + 2 * cp);
        }
    }
    // stage 32 input rows: g_h1 row = src*T1 + 5*(t0+r) + k
    for (int idx = t; idx < 32 * (C1 / 4); idx += 256) {
        int r = idx >> 5, c4 = idx & 31;
        const float* src_row = g_h1 + ((size_t)src * T1 + 5 * (t0 + r) + k) * C1;
        ((float4*)xs)[idx] = *(const float4*)(src_row + c4 * 4);
    }
    __syncthreads();

    unsigned long long acc[4][2];    // [row][ch even/odd]
#pragma unroll
    for (int j = 0; j < 4; j++) { acc[j][0] = 0ULL; acc[j][1] = 0ULL; }

#pragma unroll 4
    for (int c2 = 0; c2 < 64; c2 += 2) {
        ulonglong2 wA = wsm[c2][chpair];       // c-pair c2:   (ch even, ch odd)
        ulonglong2 wB = wsm[c2 + 1][chpair];   // c-pair c2+1
#pragma unroll
        for (int j = 0; j < 4; j++) {
            ulonglong2 xv = *(const ulonglong2*)&xs[(jq * 4 + j) * C1 + 2 * c2];
            acc[j][0] = fma2(xv.x, wA.x, acc[j][0]);
            acc[j][1] = fma2(xv.x, wA.y, acc[j][1]);
            acc[j][0] = fma2(xv.y, wB.x, acc[j][0]);
            acc[j][1] = fma2(xv.y, wB.y, acc[j][1]);
        }
    }

    float* outp = g_c2p[k];
    int ch = chb + 2 * chpair;
#pragma unroll
    for (int j = 0; j < 4; j++) {
        float2 o2 = make_float2(pksum(acc[j][0]), pksum(acc[j][1]));
        *(float2*)&outp[(size_t)(R0 + jq * 4 + j) * C2 + ch] = o2;
    }
}

// ---------------------------------------------------------------------------
// Kernel B2: sum conv2 partials + bias + layernorm(1024) + silu.
// 640 blocks x 256 thr.
// ---------------------------------------------------------------------------
__global__ void ln2_silu(const float* __restrict__ bias,
                         const float* __restrict__ lng,
                         const float* __restrict__ lnb,
                         float* __restrict__ out_vp) {
    __shared__ float red[2][8];
    int row = blockIdx.x;
    int src = row >> 7;
    int t = threadIdx.x, lane = t & 31, wid = t >> 5;
    int ch = 4 * t;
    size_t off = (size_t)row * C2 + ch;

    float4 v = *(const float4*)&bias[ch];
#pragma unroll
    for (int k = 0; k < 3; k++) {
        float4 p = *(const float4*)&g_c2p[k][off];
        v.x += p.x; v.y += p.y; v.z += p.z; v.w += p.w;
    }
    float s  = v.x + v.y + v.z + v.w;
    float s2 = v.x * v.x + v.y * v.y + v.z * v.z + v.w * v.w;
#pragma unroll
    for (int o = 16; o; o >>= 1) {
        s  += __shfl_xor_sync(0xffffffffu, s,  o);
        s2 += __shfl_xor_sync(0xffffffffu, s2, o);
    }
    if (lane == 0) { red[0][wid] = s; red[1][wid] = s2; }
    __syncthreads();
    float sum = 0.f, sumsq = 0.f;
#pragma unroll
    for (int q = 0; q < 8; q++) { sum += red[0][q]; sumsq += red[1][q]; }
    float m   = sum * (1.0f / C2);
    float var = sumsq * (1.0f / C2) - m * m;
    float rs  = rsqrtf(var + 1e-3f);

    float4 g4 = *(const float4*)&lng[ch];
    float4 b4 = *(const float4*)&lnb[ch];
    float4 o4;
    o4.x = silu_f((v.x - m) * rs * g4.x + b4.x);
    o4.y = silu_f((v.y - m) * rs * g4.y + b4.y);
    o4.z = silu_f((v.z - m) * rs * g4.z + b4.z);
    o4.w = silu_f((v.w - m) * rs * g4.w + b4.w);

    if (src < 4) {
        *(float4*)&out_vp[off] = o4;
    } else {
        *(float4*)&g_sp[(size_t)(row - 4 * T2) * C2 + ch] = o4;
    }
}

// ---------------------------------------------------------------------------
// Kernel C: similarity partials per 128-d chunk. Reads vp from output buffer.
// 512 blocks (dc8, b4, jt4, it4) x 256 thr; 32x32 tile, 2x2 per thread.
// ---------------------------------------------------------------------------
__device__ __forceinline__ float sgnx(float a, float s) {
    float b = a + s;
    unsigned int x = (__float_as_uint(a) ^ __float_as_uint(b));
    return __uint_as_float((x & 0x80000000u) | 0x3f800000u);
}

__global__ void sim_kernel(const float* __restrict__ vp) {
    __shared__ float vps[32][132];
    __shared__ float sps[32][132];

    int blk = blockIdx.x;
    int dc = blk >> 6;
    int b  = (blk >> 4) & 3;
    int jt = (blk >> 2) & 3;
    int it = blk & 3;
    int i0 = it * 32, j0 = jt * 32;
    int d0 = dc * 128;
    int t  = threadIdx.x;
    int ti = t & 15;
    int tj = t >> 4;

    for (int e = t; e < 32 * 32; e += 256) {
        int r = e >> 5, c4 = e & 31;
        *(float4*)&vps[r][c4 * 4] =
            *(const float4*)&vp[((size_t)(b * T2 + i0 + r)) * C2 + d0 + c4 * 4];
        *(float4*)&sps[r][c4 * 4] =
            *(const float4*)&g_sp[(size_t)(j0 + r) * C2 + d0 + c4 * 4];
    }
    __syncthreads();

    float a00 = 0.f, a01 = 0.f, a10 = 0.f, a11 = 0.f;
#pragma unroll 4
    for (int c4 = 0; c4 < 32; c4++) {
        float4 v0 = *(const float4*)&vps[ti][c4 * 4];
        float4 v1 = *(const float4*)&vps[ti + 16][c4 * 4];
        float4 s0 = *(const float4*)&sps[tj][c4 * 4];
        float4 s1 = *(const float4*)&sps[tj + 16][c4 * 4];
        a00 += sgnx(v0.x, s0.x) + sgnx(v0.y, s0.y) + sgnx(v0.z, s0.z) + sgnx(v0.w, s0.w);
        a01 += sgnx(v0.x, s1.x) + sgnx(v0.y, s1.y) + sgnx(v0.z, s1.z) + sgnx(v0.w, s1.w);
        a10 += sgnx(v1.x, s0.x) + sgnx(v1.y, s0.y) + sgnx(v1.z, s0.z) + sgnx(v1.w, s0.w);
        a11 += sgnx(v1.x, s1.x) + sgnx(v1.y, s1.y) + sgnx(v1.z, s1.z) + sgnx(v1.w, s1.w);
    }

    float* Sp = g_S8[dc] + (size_t)b * T2 * T2;
    Sp[(size_t)(j0 + tj) * T2 + (i0 + ti)]            = a00;
    Sp[(size_t)(j0 + tj) * T2 + (i0 + ti + 16)]       = a10;
    Sp[(size_t)(j0 + tj + 16) * T2 + (i0 + ti)]       = a01;
    Sp[(size_t)(j0 + tj + 16) * T2 + (i0 + ti + 16)]  = a11;
}

// ---------------------------------------------------------------------------
// Kernel D: softmax (summing S8 partials) + scores @ vp + silu(attn * sp)
// 512 blocks (b4, jg16 of 8 rows, dq8 of 128 d) x 128 thr (1 float each).
// ---------------------------------------------------------------------------
__global__ void attn_kernel(float* __restrict__ out, const float* __restrict__ vp) {
    __shared__ float sc[8][T2];

    int blk = blockIdx.x;
    int b  = blk >> 7;
    int jg = (blk >> 3) & 15;
    int dq = blk & 7;
    int j0 = jg * 8;
    int d0 = dq * 128;

    int t = threadIdx.x, lane = t & 31, wrp = t >> 5;

#pragma unroll
    for (int rr = 0; rr < 2; rr++) {       // 4 warps x 2 rows
        int j = j0 + wrp * 2 + rr;
        float v[4];
#pragma unroll
        for (int u = 0; u < 4; u++) {
            float s = 0.f;
#pragma unroll
            for (int dc = 0; dc < 8; dc++)
                s += g_S8[dc][((size_t)b * T2 + j) * T2 + lane + 32 * u];
            v[u] = s * (1.0f / 1024.0f);
        }
        float mx = fmaxf(fmaxf(v[0], v[1]), fmaxf(v[2], v[3]));
#pragma unroll
        for (int o = 16; o; o >>= 1)
            mx = fmaxf(mx, __shfl_xor_sync(0xffffffffu, mx, o));
        float sum = 0.f;
#pragma unroll
        for (int u = 0; u < 4; u++) { v[u] = expf(v[u] - mx); sum += v[u]; }
#pragma unroll
        for (int o = 16; o; o >>= 1)
            sum += __shfl_xor_sync(0xffffffffu, sum, o);
        float invs = 1.0f / sum;
#pragma unroll
        for (int u = 0; u < 4; u++) sc[wrp * 2 + rr][lane + 32 * u] = v[u] * invs;
    }
    __syncthreads();

    int d = d0 + t;
    float acc[8];
#pragma unroll
    for (int jl = 0; jl < 8; jl++) acc[jl] = 0.f;

    const float* vpb = vp + (size_t)b * T2 * C2 + d;
#pragma unroll 8
    for (int i = 0; i < T2; i++) {
        float v = vpb[(size_t)i * C2];
#pragma unroll
        for (int jl = 0; jl < 8; jl++)
            acc[jl] += sc[jl][i] * v;
    }

#pragma unroll
    for (int jl = 0; jl < 8; jl++) {
        int j = j0 + jl;
        float spv = g_sp[(size_t)j * C2 + d];
        out[((size_t)(b * T2 + j)) * C2 + d] = silu_f(acc[jl] * spv);
    }
}

// ---------------------------------------------------------------------------
extern "C" void kernel_launch(void* const* d_in, const int* in_sizes, int n_in,
                              void* d_out, int out_size) {
    const float* values  = (const float*)d_in[0];
    const float* symbols = (const float*)d_in[1];
    const float* c1w     = (const float*)d_in[2];
    const float* c1b     = (const float*)d_in[3];
    const float* l1g     = (const float*)d_in[4];
    const float* l1b     = (const float*)d_in[5];
    const float* c2w     = (const float*)d_in[6];
    const float* c2b     = (const float*)d_in[7];
    const float* l2g     = (const float*)d_in[8];
    const float* l2b     = (const float*)d_in[9];
    float* out = (float*)d_out;
    float* out_vp = out + (size_t)BATCH * T2 * C2;

    prepack_w2<<<768, 256>>>(c2w);                    // launch 1
    prepack_w1<<<320, 256>>>(c1w, 0);                 // launch 2
    prepack_w1<<<320, 256>>>(c1w, 320 * 256);         // launch 3
    conv1_raw<<<800, 256>>>(values, symbols);         // launch 4 -> ncu capture
    ln1_silu<<<400, 256>>>(c1b, l1g, l1b);
    conv2_raw<<<960, 256>>>();
    ln2_silu<<<640, 256>>>(c2b, l2g, l2b, out_vp);
    sim_kernel<<<512, 256>>>(out_vp);
    attn_kernel<<<512, 128>>>(out, out_vp);
}

// round 17
// speedup vs baseline: 1.0851x; 1.0851x over previous
#include <cuda_runtime.h>
#include <math.h>

#define BATCH 4
#define T_IN 1920
#define E_IN 512
#define C1 128
#define T1 640
#define C2 1024
#define T2 128

// Scratch (device globals; allocations forbidden)
__device__ float  g_h1[5 * T1 * C1];             // conv1+ln1+silu output
__device__ float  g_c1p[8][5 * T1 * C1];         // conv1 partials per E-eighth
__device__ float  g_c2p[3][5 * T2 * C2];         // conv2 partials per k-tap
__device__ float  g_vp[BATCH * T2 * C2];         // values_projected
__device__ float  g_sp[T2 * C2];                 // symbol_projected
__device__ float  g_S8[8][BATCH * T2 * T2];      // similarity partials per 128-d chunk
__device__ float2 g_wpk1[5 * 256 * 128];         // conv1 w c-pair packed
__device__ float2 g_wpk2[3 * 64 * 1024];         // conv2 w c-pair packed

__device__ __forceinline__ float silu_f(float y) { return y / (1.0f + expf(-y)); }

__device__ __forceinline__ unsigned long long fma2(unsigned long long a,
                                                   unsigned long long b,
                                                   unsigned long long c) {
    unsigned long long d;
    asm("fma.rn.f32x2 %0, %1, %2, %3;" : "=l"(d) : "l"(a), "l"(b), "l"(c));
    return d;
}
__device__ __forceinline__ float pksum(unsigned long long p) {
    unsigned int lo, hi;
    asm("mov.b64 {%0, %1}, %2;" : "=r"(lo), "=r"(hi) : "l"(p));
    return __uint_as_float(lo) + __uint_as_float(hi);
}

// ---------------------------------------------------------------------------
// Kernel 0: repack conv weights into c-pair (f32x2) layout
// ---------------------------------------------------------------------------
__global__ void prepack(const float* __restrict__ w1, const float* __restrict__ w2) {
    int idx = blockIdx.x * 256 + threadIdx.x;
    if (idx < 5 * 256 * 128) {
        int o  = idx & 127;
        int c2 = (idx >> 7) & 255;
        int k  = idx >> 15;
        const float* p = w1 + ((size_t)(k * 512 + 2 * c2)) * 128 + o;
        g_wpk1[idx] = make_float2(p[0], p[128]);
    }
    if (idx < 3 * 64 * 1024) {
        int o  = idx & 1023;
        int c2 = (idx >> 10) & 63;
        int k  = idx >> 16;
        const float* p = w2 + ((size_t)(k * 128 + 2 * c2)) * 1024 + o;
        g_wpk2[idx] = make_float2(p[0], p[1024]);
    }
}

// ---------------------------------------------------------------------------
// Kernel A1: conv1 partials with cp.async DOUBLE-BUFFERED weight pipeline.
// grid = 5src x 20tg x 8eh = 800 blocks, 256 thr, 4 CTAs/SM (smem 41KB).
// 20 slices (5k x 4): 8KB weight slice prefetched via cp.async while the
// previous slice is computed. Warp tile: 8 ts x 2 ch (proven).
// ---------------------------------------------------------------------------
#define C1TS 32
#define C1ROWS (3 * (C1TS - 1) + 5)   // 98
#define EC 64

#define CONV1_PREFETCH(s, b)                                                        \
    do {                                                                            \
        int pk = (s) >> 2;                                                          \
        const float4* psrc = (const float4*)(g_wpk1 +                               \
            ((size_t)(pk * 256 + eh * 32 + ((s) & 3) * 8)) * 128);                  \
        unsigned int pdst = wsm_base + (unsigned int)(b) * 8192u + t * 16u;         \
        asm volatile("cp.async.cg.shared.global [%0], [%1], 16;"                    \
                     :: "r"(pdst), "l"(psrc + t) : "memory");                       \
        asm volatile("cp.async.cg.shared.global [%0], [%1], 16;"                    \
                     :: "r"(pdst + 4096u), "l"(psrc + t + 256) : "memory");         \
        asm volatile("cp.async.commit_group;" ::: "memory");                        \
    } while (0)

__global__ void __launch_bounds__(256, 4) conv1_raw(const float* __restrict__ values,
                                                    const float* __restrict__ symbols) {
    __shared__ float  xs[C1ROWS * EC];   // 25088 B
    __shared__ float2 wsm[2][8 * 128];   // 2 x 8192 B

    int blk = blockIdx.x;               // (src*20 + tg)*8 + eh
    int eh  = blk & 7;
    int st  = blk >> 3;                 // 0..99
    int src = st / 20;
    int tg  = st % 20;
    int t0  = tg * C1TS;
    const float* x = (src < 4) ? (values + (size_t)src * T_IN * E_IN) : symbols;
    int base_row = t0 * 3 - 1;
    int col0 = eh * EC;

    int t    = threadIdx.x;
    int lane = t & 31;
    int wrp  = t >> 5;                  // 0..7
    int tsg  = wrp & 3;                 // 4 ts-groups
    int chh  = wrp >> 2;                // 2 channel halves
    int ch0  = chh * 64 + lane * 2;
    int ts0  = tsg * 8;                 // 8 timesteps per warp

    unsigned int wsm_base = (unsigned int)__cvta_generic_to_shared(&wsm[0][0]);

    // kick off slice 0 prefetch before x staging (overlap)
    CONV1_PREFETCH(0, 0);

    // stage 98 rows x 64 cols of x
    for (int idx = t; idx < C1ROWS * (EC / 4); idx += 256) {
        int r  = idx >> 4;              // EC/4 = 16
        int c4 = idx & 15;
        int gr = base_row + r;
        float4 v = make_float4(0.f, 0.f, 0.f, 0.f);
        if (gr >= 0 && gr < T_IN)
            v = *(const float4*)(x + (size_t)gr * E_IN + col0 + c4 * 4);
        ((float4*)xs)[idx] = v;
    }

    unsigned long long acc[8][2];       // [ts][ch]
#pragma unroll
    for (int j = 0; j < 8; j++) { acc[j][0] = 0ULL; acc[j][1] = 0ULL; }

    for (int s = 0; s < 20; s++) {
        int b = s & 1;
        if (s < 19) {
            CONV1_PREFETCH(s + 1, b ^ 1);
            asm volatile("cp.async.wait_group 1;" ::: "memory");
        } else {
            asm volatile("cp.async.wait_group 0;" ::: "memory");
        }
        __syncthreads();                // slice s visible; prev buffer free for writers

        int k    = s >> 2;
        int xoff = (s & 3) * 16;
        const float2* wbuf = wsm[b];
#pragma unroll
        for (int c2 = 0; c2 < 8; c2 += 2) {
            ulonglong2 w0 = *(const ulonglong2*)&wbuf[c2 * 128 + ch0];
            ulonglong2 w1 = *(const ulonglong2*)&wbuf[(c2 + 1) * 128 + ch0];
#pragma unroll
            for (int j = 0; j < 8; j++) {
                ulonglong2 xv = *(const ulonglong2*)
                    &xs[(3 * (ts0 + j) + k) * EC + xoff + 2 * c2];
                acc[j][0] = fma2(xv.x, w0.x, acc[j][0]);
                acc[j][1] = fma2(xv.x, w0.y, acc[j][1]);
                acc[j][0] = fma2(xv.y, w1.x, acc[j][0]);
                acc[j][1] = fma2(xv.y, w1.y, acc[j][1]);
            }
        }
        __syncthreads();                // all readers done before buffer is overwritten
    }

    float* outp = g_c1p[eh];
#pragma unroll
    for (int j = 0; j < 8; j++) {
        float2 o2 = make_float2(pksum(acc[j][0]), pksum(acc[j][1]));
        *(float2*)&outp[((size_t)src * T1 + (t0 + ts0 + j)) * C1 + ch0] = o2;
    }
}

// ---------------------------------------------------------------------------
// Kernel A2: sum conv1 partials + bias + layernorm(128) + silu -> g_h1
// 400 blocks x 256 thr; warp = 1 row, lane = 4 channels (warp-local LN).
// ---------------------------------------------------------------------------
__global__ void ln1_silu(const float* __restrict__ bias,
                         const float* __restrict__ lng,
                         const float* __restrict__ lnb) {
    int row  = blockIdx.x * 8 + (threadIdx.x >> 5);   // 0..3199
    int lane = threadIdx.x & 31;
    int ch0  = lane * 4;
    size_t off = (size_t)row * C1 + ch0;

    float4 v = *(const float4*)&bias[ch0];
#pragma unroll
    for (int eh = 0; eh < 8; eh++) {
        float4 p = *(const float4*)&g_c1p[eh][off];
        v.x += p.x; v.y += p.y; v.z += p.z; v.w += p.w;
    }
    float s  = v.x + v.y + v.z + v.w;
    float s2 = v.x * v.x + v.y * v.y + v.z * v.z + v.w * v.w;
#pragma unroll
    for (int o = 16; o; o >>= 1) {
        s  += __shfl_xor_sync(0xffffffffu, s,  o);
        s2 += __shfl_xor_sync(0xffffffffu, s2, o);
    }
    float m   = s * (1.0f / C1);
    float var = s2 * (1.0f / C1) - m * m;
    float rs  = rsqrtf(var + 1e-3f);
    float4 g4 = *(const float4*)&lng[ch0];
    float4 b4 = *(const float4*)&lnb[ch0];
    float4 o4;
    o4.x = silu_f((v.x - m) * rs * g4.x + b4.x);
    o4.y = silu_f((v.y - m) * rs * g4.y + b4.y);
    o4.z = silu_f((v.z - m) * rs * g4.z + b4.z);
    o4.w = silu_f((v.w - m) * rs * g4.w + b4.w);
    *(float4*)&g_h1[off] = o4;
}

// ---------------------------------------------------------------------------
// Kernel B1: conv2 partials, smem-staged weights (exact R9 best-total config).
// grid = 20 rowgroups(32 rows) x 16 chq(64 ch) x 3 k = 960 blocks, 256 thr.
// ---------------------------------------------------------------------------
__global__ void __launch_bounds__(256, 4) conv2_raw() {
    __shared__ ulonglong2 wsm[64][32];   // [c2][chpair]   32KB
    __shared__ float xs[32 * C1];        // 32 input rows  16KB

    int blk = blockIdx.x;
    int k   = blk % 3;
    int r1  = blk / 3;               // 0..319
    int chq = r1 & 15;               // 16 channel slices of 64
    int rg  = r1 >> 4;               // 0..19
    int R0  = rg * 32;               // global output row (src*T2 + t2)
    int src = R0 >> 7;
    int t0  = R0 & 127;
    int chb = chq * 64;

    int t      = threadIdx.x;
    int chpair = t & 31;             // ch = chb + 2*chpair (+1)
    int jq     = t >> 5;             // 0..7 -> rows jq*4 .. jq*4+3

    {
        const float2* wsrc = g_wpk2 + (size_t)(k * 64) * 1024 + chb;
        for (int idx = t; idx < 64 * 32; idx += 256) {
            int c2 = idx >> 5, cp = idx & 31;
            wsm[c2][cp] = *(const ulonglong2*)(wsrc + (size_t)c2 * 1024 + 2 * cp);
        }
    }
    for (int idx = t; idx < 32 * (C1 / 4); idx += 256) {
        int r = idx >> 5, c4 = idx & 31;
        const float* src_row = g_h1 + ((size_t)src * T1 + 5 * (t0 + r) + k) * C1;
        ((float4*)xs)[idx] = *(const float4*)(src_row + c4 * 4);
    }
    __syncthreads();

    unsigned long long acc[4][2];    // [row][ch even/odd]
#pragma unroll
    for (int j = 0; j < 4; j++) { acc[j][0] = 0ULL; acc[j][1] = 0ULL; }

#pragma unroll 4
    for (int c2 = 0; c2 < 64; c2 += 2) {
        ulonglong2 wA = wsm[c2][chpair];
        ulonglong2 wB = wsm[c2 + 1][chpair];
#pragma unroll
        for (int j = 0; j < 4; j++) {
            ulonglong2 xv = *(const ulonglong2*)&xs[(jq * 4 + j) * C1 + 2 * c2];
            acc[j][0] = fma2(xv.x, wA.x, acc[j][0]);
            acc[j][1] = fma2(xv.x, wA.y, acc[j][1]);
            acc[j][0] = fma2(xv.y, wB.x, acc[j][0]);
            acc[j][1] = fma2(xv.y, wB.y, acc[j][1]);
        }
    }

    float* outp = g_c2p[k];
    int ch = chb + 2 * chpair;
#pragma unroll
    for (int j = 0; j < 4; j++) {
        float2 o2 = make_float2(pksum(acc[j][0]), pksum(acc[j][1]));
        *(float2*)&outp[(size_t)(R0 + jq * 4 + j) * C2 + ch] = o2;
    }
}

// ---------------------------------------------------------------------------
// Kernel B2: sum conv2 partials + bias + layernorm(1024) + silu
// 640 blocks x 256 thr.
// ---------------------------------------------------------------------------
__global__ void ln2_silu(const float* __restrict__ bias,
                         const float* __restrict__ lng,
                         const float* __restrict__ lnb,
                         float* __restrict__ out_vp_copy) {
    __shared__ float red[2][8];
    int row = blockIdx.x;
    int src = row >> 7;
    int t = threadIdx.x, lane = t & 31, wid = t >> 5;
    int ch = 4 * t;
    size_t off = (size_t)row * C2 + ch;

    float4 v = *(const float4*)&bias[ch];
#pragma unroll
    for (int k = 0; k < 3; k++) {
        float4 p = *(const float4*)&g_c2p[k][off];
        v.x += p.x; v.y += p.y; v.z += p.z; v.w += p.w;
    }
    float s  = v.x + v.y + v.z + v.w;
    float s2 = v.x * v.x + v.y * v.y + v.z * v.z + v.w * v.w;
#pragma unroll
    for (int o = 16; o; o >>= 1) {
        s  += __shfl_xor_sync(0xffffffffu, s,  o);
        s2 += __shfl_xor_sync(0xffffffffu, s2, o);
    }
    if (lane == 0) { red[0][wid] = s; red[1][wid] = s2; }
    __syncthreads();
    float sum = 0.f, sumsq = 0.f;
#pragma unroll
    for (int q = 0; q < 8; q++) { sum += red[0][q]; sumsq += red[1][q]; }
    float m   = sum * (1.0f / C2);
    float var = sumsq * (1.0f / C2) - m * m;
    float rs  = rsqrtf(var + 1e-3f);

    float4 g4 = *(const float4*)&lng[ch];
    float4 b4 = *(const float4*)&lnb[ch];
    float4 o4;
    o4.x = silu_f((v.x - m) * rs * g4.x + b4.x);
    o4.y = silu_f((v.y - m) * rs * g4.y + b4.y);
    o4.z = silu_f((v.z - m) * rs * g4.z + b4.z);
    o4.w = silu_f((v.w - m) * rs * g4.w + b4.w);

    if (src < 4) {
        *(float4*)&g_vp[off] = o4;
        *(float4*)&out_vp_copy[off] = o4;
    } else {
        *(float4*)&g_sp[(size_t)(row - 4 * T2) * C2 + ch] = o4;
    }
}

// ---------------------------------------------------------------------------
// Kernel C: similarity partials per 128-d chunk.
// 512 blocks (dc8, b4, jt4, it4) x 256 thr; 32x32 tile, 2x2 per thread.
// ---------------------------------------------------------------------------
__device__ __forceinline__ float sgnx(float a, float s) {
    float b = a + s;
    unsigned int x = (__float_as_uint(a) ^ __float_as_uint(b));
    return __uint_as_float((x & 0x80000000u) | 0x3f800000u);
}

__global__ void sim_kernel() {
    __shared__ float vps[32][132];
    __shared__ float sps[32][132];

    int blk = blockIdx.x;
    int dc = blk >> 6;
    int b  = (blk >> 4) & 3;
    int jt = (blk >> 2) & 3;
    int it = blk & 3;
    int i0 = it * 32, j0 = jt * 32;
    int d0 = dc * 128;
    int t  = threadIdx.x;
    int ti = t & 15;
    int tj = t >> 4;

    for (int e = t; e < 32 * 32; e += 256) {
        int r = e >> 5, c4 = e & 31;
        *(float4*)&vps[r][c4 * 4] =
            *(const float4*)&g_vp[((size_t)(b * T2 + i0 + r)) * C2 + d0 + c4 * 4];
        *(float4*)&sps[r][c4 * 4] =
            *(const float4*)&g_sp[(size_t)(j0 + r) * C2 + d0 + c4 * 4];
    }
    __syncthreads();

    float a00 = 0.f, a01 = 0.f, a10 = 0.f, a11 = 0.f;
#pragma unroll 4
    for (int c4 = 0; c4 < 32; c4++) {
        float4 v0 = *(const float4*)&vps[ti][c4 * 4];
        float4 v1 = *(const float4*)&vps[ti + 16][c4 * 4];
        float4 s0 = *(const float4*)&sps[tj][c4 * 4];
        float4 s1 = *(const float4*)&sps[tj + 16][c4 * 4];
        a00 += sgnx(v0.x, s0.x) + sgnx(v0.y, s0.y) + sgnx(v0.z, s0.z) + sgnx(v0.w, s0.w);
        a01 += sgnx(v0.x, s1.x) + sgnx(v0.y, s1.y) + sgnx(v0.z, s1.z) + sgnx(v0.w, s1.w);
        a10 += sgnx(v1.x, s0.x) + sgnx(v1.y, s0.y) + sgnx(v1.z, s0.z) + sgnx(v1.w, s0.w);
        a11 += sgnx(v1.x, s1.x) + sgnx(v1.y, s1.y) + sgnx(v1.z, s1.z) + sgnx(v1.w, s1.w);
    }

    float* Sp = g_S8[dc] + (size_t)b * T2 * T2;
    Sp[(size_t)(j0 + tj) * T2 + (i0 + ti)]            = a00;
    Sp[(size_t)(j0 + tj) * T2 + (i0 + ti + 16)]       = a10;
    Sp[(size_t)(j0 + tj + 16) * T2 + (i0 + ti)]       = a01;
    Sp[(size_t)(j0 + tj + 16) * T2 + (i0 + ti + 16)]  = a11;
}

// ---------------------------------------------------------------------------
// Kernel D: softmax (summing S8 partials) + scores @ vp + silu(attn * sp)
// 512 blocks (b4, jg16 of 8 rows, dq8 of 128 d) x 128 thr (1 float each).
// ---------------------------------------------------------------------------
__global__ void attn_kernel(float* __restrict__ out) {
    __shared__ float sc[8][T2];

    int blk = blockIdx.x;
    int b  = blk >> 7;
    int jg = (blk >> 3) & 15;
    int dq = blk & 7;
    int j0 = jg * 8;
    int d0 = dq * 128;

    int t = threadIdx.x, lane = t & 31, wrp = t >> 5;

#pragma unroll
    for (int rr = 0; rr < 2; rr++) {       // 4 warps x 2 rows
        int j = j0 + wrp * 2 + rr;
        float v[4];
#pragma unroll
        for (int u = 0; u < 4; u++) {
            float s = 0.f;
#pragma unroll
            for (int dc = 0; dc < 8; dc++)
                s += g_S8[dc][((size_t)b * T2 + j) * T2 + lane + 32 * u];
            v[u] = s * (1.0f / 1024.0f);
        }
        float mx = fmaxf(fmaxf(v[0], v[1]), fmaxf(v[2], v[3]));
#pragma unroll
        for (int o = 16; o; o >>= 1)
            mx = fmaxf(mx, __shfl_xor_sync(0xffffffffu, mx, o));
        float sum = 0.f;
#pragma unroll
        for (int u = 0; u < 4; u++) { v[u] = expf(v[u] - mx); sum += v[u]; }
#pragma unroll
        for (int o = 16; o; o >>= 1)
            sum += __shfl_xor_sync(0xffffffffu, sum, o);
        float invs = 1.0f / sum;
#pragma unroll
        for (int u = 0; u < 4; u++) sc[wrp * 2 + rr][lane + 32 * u] = v[u] * invs;
    }
    __syncthreads();

    int d = d0 + t;
    float acc[8];
#pragma unroll
    for (int jl = 0; jl < 8; jl++) acc[jl] = 0.f;

    const float* vpb = g_vp + (size_t)b * T2 * C2 + d;
#pragma unroll 8
    for (int i = 0; i < T2; i++) {
        float v = vpb[(size_t)i * C2];
#pragma unroll
        for (int jl = 0; jl < 8; jl++)
            acc[jl] += sc[jl][i] * v;
    }

#pragma unroll
    for (int jl = 0; jl < 8; jl++) {
        int j = j0 + jl;
        float spv = g_sp[(size_t)j * C2 + d];
        out[((size_t)(b * T2 + j)) * C2 + d] = silu_f(acc[jl] * spv);
    }
}

// ---------------------------------------------------------------------------
extern "C" void kernel_launch(void* const* d_in, const int* in_sizes, int n_in,
                              void* d_out, int out_size) {
    const float* values  = (const float*)d_in[0];
    const float* symbols = (const float*)d_in[1];
    const float* c1w     = (const float*)d_in[2];
    const float* c1b     = (const float*)d_in[3];
    const float* l1g     = (const float*)d_in[4];
    const float* l1b     = (const float*)d_in[5];
    const float* c2w     = (const float*)d_in[6];
    const float* c2b     = (const float*)d_in[7];
    const float* l2g     = (const float*)d_in[8];
    const float* l2b     = (const float*)d_in[9];
    float* out = (float*)d_out;
    float* out_vp = out + (size_t)BATCH * T2 * C2;

    prepack<<<768, 256>>>(c1w, c2w);
    conv1_raw<<<800, 256>>>(values, symbols);
    ln1_silu<<<400, 256>>>(c1b, l1g, l1b);
    conv2_raw<<<960, 256>>>();
    ln2_silu<<<640, 256>>>(c2b, l2g, l2b, out_vp);
    sim_kernel<<<512, 256>>>();
    attn_kernel<<<512, 128>>>(out);
}